// round 7
// baseline (speedup 1.0000x reference)
#include <cuda_runtime.h>
#include <cuda_bf16.h>

// Problem constants (fixed by reference)
#define BB      8
#define NN      2048
#define DD      256
#define KSTEPS  10
#define OUTD    15
#define MAXN    256
#define TOTROWS (BB * NN)   // 16384

// ---- static device scratch (no allocations allowed) ----
__device__ float g_H  [TOTROWS * DD];   // 16 MB  current node states (fp32)
__device__ float g_AH [TOTROWS * DD];   // 16 MB  A @ H result per step
__device__ short g_col[TOTROWS * MAXN]; //  8 MB  padded CSR column indices
__device__ int   g_deg[TOTROWS];
__device__ float g_inv[TOTROWS];        // 1 / max(deg, 1)

// =====================================================================
// Kernel 1: adjacency build. One warp per row: ballot-compact nonzero
// columns of (Yr!=0 || Yi!=0), excluding the diagonal.
// =====================================================================
__global__ void __launch_bounds__(256) adj_kernel(const float* __restrict__ Yr,
                                                  const float* __restrict__ Yi) {
    const int warp = (blockIdx.x * blockDim.x + threadIdx.x) >> 5; // global row
    const int lane = threadIdx.x & 31;
    if (warp >= TOTROWS) return;
    const int i = warp & (NN - 1); // row within batch
    const float* yr = Yr + (size_t)warp * NN;
    const float* yi = Yi + (size_t)warp * NN;
    short* cols = g_col + (size_t)warp * MAXN;

    int count = 0;
    #pragma unroll 4
    for (int j0 = 0; j0 < NN; j0 += 32) {
        const int j = j0 + lane;
        const bool nz = (j != i) && ((yr[j] != 0.0f) || (yi[j] != 0.0f));
        const unsigned m = __ballot_sync(0xffffffffu, nz);
        if (nz) {
            const int pos = count + __popc(m & ((1u << lane) - 1u));
            if (pos < MAXN) cols[pos] = (short)j;
        }
        count += __popc(m);
    }
    if (lane == 0) {
        g_deg[warp] = count < MAXN ? count : MAXN;
        g_inv[warp] = 1.0f / (float)(count > 1 ? count : 1);
    }
}

// =====================================================================
// Kernel 2: role-selected embedding. One block per node, thread = d.
// H[n,d] = tanh(f0*W[r,0,d] + f1*W[r,1,d] + b[r,d])
// =====================================================================
__global__ void __launch_bounds__(256) emb_kernel(const int*   __restrict__ bus_type,
                                                  const float* __restrict__ features,
                                                  const float* __restrict__ W_emb,
                                                  const float* __restrict__ b_emb) {
    const int node = blockIdx.x;
    const int d = threadIdx.x;
    const int r = bus_type[node] - 1;          // 0..2
    const float f0 = features[node * 2 + 0];
    const float f1 = features[node * 2 + 1];
    const float w0 = W_emb[(r * 2 + 0) * DD + d];
    const float w1 = W_emb[(r * 2 + 1) * DD + d];
    const float h = tanhf(fmaf(f0, w0, fmaf(f1, w1, b_emb[r * DD + d])));
    g_H[(size_t)node * DD + d] = h;
}

// =====================================================================
// Kernel 3: SpMM  AH[row,:] = inv_deg * sum_{j in nbrs(row)} H[j,:]
// One warp per row (4 rows per warp sequentially). Each lane owns
// d = lane*4..+3 and d+128..+131 (two float4 accumulators).
// Gathers are 128B-coalesced per j and hit L2 (H is L2-resident).
// =====================================================================
__device__ __forceinline__ void add4(float4& a, const float4 v) {
    a.x += v.x; a.y += v.y; a.z += v.z; a.w += v.w;
}

__global__ void __launch_bounds__(256) spmm_kernel() {
    const int lane = threadIdx.x & 31;
    const int warp = threadIdx.x >> 5;
    const int row0 = blockIdx.x * 32 + warp * 4;

    for (int rr = 0; rr < 4; ++rr) {
        const int row = row0 + rr;
        const int b = row >> 11;                       // row / 2048
        const float* __restrict__ Hb = g_H + (size_t)b * NN * DD;
        const short* __restrict__ cols = g_col + (size_t)row * MAXN;
        const int deg = g_deg[row];
        const float inv = g_inv[row];

        float4 aLo = make_float4(0.f, 0.f, 0.f, 0.f);
        float4 aHi = make_float4(0.f, 0.f, 0.f, 0.f);

        int t = 0;
        for (; t + 4 <= deg; t += 4) {
            const int j0 = cols[t], j1 = cols[t + 1], j2 = cols[t + 2], j3 = cols[t + 3];
            const float4* p0 = (const float4*)(Hb + (size_t)j0 * DD);
            const float4* p1 = (const float4*)(Hb + (size_t)j1 * DD);
            const float4* p2 = (const float4*)(Hb + (size_t)j2 * DD);
            const float4* p3 = (const float4*)(Hb + (size_t)j3 * DD);
            const float4 x0 = p0[lane], y0 = p0[lane + 32];
            const float4 x1 = p1[lane], y1 = p1[lane + 32];
            const float4 x2 = p2[lane], y2 = p2[lane + 32];
            const float4 x3 = p3[lane], y3 = p3[lane + 32];
            add4(aLo, x0); add4(aHi, y0);
            add4(aLo, x1); add4(aHi, y1);
            add4(aLo, x2); add4(aHi, y2);
            add4(aLo, x3); add4(aHi, y3);
        }
        for (; t < deg; ++t) {
            const int j0 = cols[t];
            const float4* p0 = (const float4*)(Hb + (size_t)j0 * DD);
            add4(aLo, p0[lane]); add4(aHi, p0[lane + 32]);
        }

        aLo.x *= inv; aLo.y *= inv; aLo.z *= inv; aLo.w *= inv;
        aHi.x *= inv; aHi.y *= inv; aHi.z *= inv; aHi.w *= inv;
        float4* outp = (float4*)(g_AH + (size_t)row * DD);
        outp[lane] = aLo;
        outp[lane + 32] = aHi;
    }
}

// =====================================================================
// Kernel 4: dense update  H += tanh(AH @ Wl + bl)   (in-place on H:
// legal because the sparse gather consumed AH, not H).
// SGEMM M=16384, N=256, K=256. CTA tile 128x128, thread tile 8x8,
// k-chunk 8, SMEM pitch 132 (bank-conflict-free stores, 16B-aligned).
// =====================================================================
__global__ void __launch_bounds__(256) update_kernel(const float* __restrict__ Wl,
                                                     const float* __restrict__ bl) {
    __shared__ float As[8][132];
    __shared__ float Bs[8][132];

    const int tid   = threadIdx.x;
    const int mBase = blockIdx.x * 128;
    const int nBase = blockIdx.y * 128;

    // load indices
    const int mA = tid >> 1;            // 0..127
    const int hA = (tid & 1) * 4;       // 0 or 4 (k offset)
    const int kB = tid >> 5;            // 0..7
    const int nB = (tid & 31) * 4;      // 0..124

    // compute indices
    const int m0 = (tid >> 4) * 8;      // 0..120
    const int n0 = (tid & 15) * 8;      // 0..120

    float acc[8][8];
    #pragma unroll
    for (int i = 0; i < 8; ++i)
        #pragma unroll
        for (int j = 0; j < 8; ++j) acc[i][j] = 0.0f;

    for (int kk = 0; kk < DD; kk += 8) {
        const float4 av = *(const float4*)(g_AH + (size_t)(mBase + mA) * DD + kk + hA);
        As[hA + 0][mA] = av.x; As[hA + 1][mA] = av.y;
        As[hA + 2][mA] = av.z; As[hA + 3][mA] = av.w;
        const float4 bv = *(const float4*)(Wl + (size_t)(kk + kB) * DD + nBase + nB);
        *(float4*)&Bs[kB][nB] = bv;
        __syncthreads();

        #pragma unroll
        for (int k = 0; k < 8; ++k) {
            const float4 a0 = *(const float4*)&As[k][m0];
            const float4 a1 = *(const float4*)&As[k][m0 + 4];
            const float4 b0 = *(const float4*)&Bs[k][n0];
            const float4 b1 = *(const float4*)&Bs[k][n0 + 4];
            const float am[8] = {a0.x, a0.y, a0.z, a0.w, a1.x, a1.y, a1.z, a1.w};
            const float bn[8] = {b0.x, b0.y, b0.z, b0.w, b1.x, b1.y, b1.z, b1.w};
            #pragma unroll
            for (int i = 0; i < 8; ++i)
                #pragma unroll
                for (int j = 0; j < 8; ++j)
                    acc[i][j] = fmaf(am[i], bn[j], acc[i][j]);
        }
        __syncthreads();
    }

    // fused epilogue: H[row, col] += tanh(acc + bl[col])
    const float4 bl0 = *(const float4*)(bl + nBase + n0);
    const float4 bl1 = *(const float4*)(bl + nBase + n0 + 4);
    const float blv[8] = {bl0.x, bl0.y, bl0.z, bl0.w, bl1.x, bl1.y, bl1.z, bl1.w};

    #pragma unroll
    for (int i = 0; i < 8; ++i) {
        float* Hrow = g_H + (size_t)(mBase + m0 + i) * DD + nBase + n0;
        float4 h0 = *(float4*)Hrow;
        float4 h1 = *(float4*)(Hrow + 4);
        h0.x += tanhf(acc[i][0] + blv[0]);
        h0.y += tanhf(acc[i][1] + blv[1]);
        h0.z += tanhf(acc[i][2] + blv[2]);
        h0.w += tanhf(acc[i][3] + blv[3]);
        h1.x += tanhf(acc[i][4] + blv[4]);
        h1.y += tanhf(acc[i][5] + blv[5]);
        h1.z += tanhf(acc[i][6] + blv[6]);
        h1.w += tanhf(acc[i][7] + blv[7]);
        *(float4*)Hrow       = h0;
        *(float4*)(Hrow + 4) = h1;
    }
}

// =====================================================================
// Kernel 5: decoder. Block = batch. Threads reduce the node mean per d
// (coalesced column sums), then 15 threads do the tiny final GEMV.
// =====================================================================
__global__ void __launch_bounds__(256) decoder_kernel(const float* __restrict__ Wd,
                                                      const float* __restrict__ bd,
                                                      float* __restrict__ out) {
    const int b = blockIdx.x;
    const int d = threadIdx.x;
    const float* Hb = g_H + (size_t)b * NN * DD;

    float s0 = 0.f, s1 = 0.f, s2 = 0.f, s3 = 0.f;
    #pragma unroll 1
    for (int n = 0; n < NN; n += 4) {
        s0 += Hb[(size_t)(n + 0) * DD + d];
        s1 += Hb[(size_t)(n + 1) * DD + d];
        s2 += Hb[(size_t)(n + 2) * DD + d];
        s3 += Hb[(size_t)(n + 3) * DD + d];
    }
    __shared__ float mean[DD];
    mean[d] = (s0 + s1 + s2 + s3) * (1.0f / (float)NN);
    __syncthreads();

    if (d < OUTD) {
        float o = bd[d];
        #pragma unroll 8
        for (int k = 0; k < DD; ++k)
            o = fmaf(mean[k], Wd[k * OUTD + d], o);
        out[b * OUTD + d] = o;
    }
}

// =====================================================================
// Launch
// Inputs (metadata order): 0 bus_type(i32), 1 Yr, 2 Yi, 3 features,
// 4 W_emb, 5 b_emb, 6 Wl, 7 bl, 8 Wd, 9 bd.  Output: float[8*15].
// =====================================================================
extern "C" void kernel_launch(void* const* d_in, const int* in_sizes, int n_in,
                              void* d_out, int out_size) {
    const int*   bus_type = (const int*)  d_in[0];
    const float* Yr       = (const float*)d_in[1];
    const float* Yi       = (const float*)d_in[2];
    const float* features = (const float*)d_in[3];
    const float* W_emb    = (const float*)d_in[4];
    const float* b_emb    = (const float*)d_in[5];
    const float* Wl       = (const float*)d_in[6];
    const float* bl       = (const float*)d_in[7];
    const float* Wd       = (const float*)d_in[8];
    const float* bd       = (const float*)d_in[9];
    float* out = (float*)d_out;

    // 1) adjacency: one warp per row
    adj_kernel<<<TOTROWS / 8, 256>>>(Yr, Yi);

    // 2) embedding: one block per node
    emb_kernel<<<TOTROWS, 256>>>(bus_type, features, W_emb, b_emb);

    // 3) K leap steps: SpMM then fused dense update (in-place H)
    for (int k = 0; k < KSTEPS; ++k) {
        spmm_kernel<<<TOTROWS / 32, 256>>>();
        update_kernel<<<dim3(TOTROWS / 128, DD / 128), 256>>>(Wl, bl);
    }

    // 4) decoder
    decoder_kernel<<<BB, 256>>>(Wd, bd, out);
}

// round 8
// speedup vs baseline: 1.1647x; 1.1647x over previous
#include <cuda_runtime.h>
#include <cuda_bf16.h>

// Problem constants (fixed by reference)
#define BB      8
#define NN      2048
#define DD      256
#define KSTEPS  10
#define OUTD    15
#define MAXN    256
#define TOTROWS (BB * NN)   // 16384

// ---- static device scratch (no allocations allowed) ----
__device__ float          g_H  [TOTROWS * DD];   // 16 MB fp32 master H
__device__ __nv_bfloat16  g_Hbf[TOTROWS * DD];   //  8 MB bf16 mirror (gather source)
__device__ float          g_AH [TOTROWS * DD];   // 16 MB A @ H result per step
__device__ short          g_col[TOTROWS * MAXN]; //  8 MB padded CSR column indices
__device__ int            g_deg[TOTROWS];
__device__ float          g_inv[TOTROWS];        // 1 / max(deg, 1)

// ---- packed f32x2 helpers (Blackwell FFMA2) ----
#define FMA2(acc, a, b) \
    asm("fma.rn.f32x2 %0, %1, %2, %0;" : "+l"(acc) : "l"(a), "l"(b))

__device__ __forceinline__ unsigned long long pack2(float x) {
    unsigned long long r;
    asm("mov.b64 %0, {%1, %1};" : "=l"(r) : "r"(__float_as_uint(x)));
    return r;
}

__device__ __forceinline__ void unpack2(unsigned long long v, float& lo, float& hi) {
    unsigned a, b;
    asm("mov.b64 {%0, %1}, %2;" : "=r"(a), "=r"(b) : "l"(v));
    lo = __uint_as_float(a);
    hi = __uint_as_float(b);
}

// =====================================================================
// Kernel 1: adjacency build. One warp per row: ballot-compact nonzero
// columns of (Yr!=0 || Yi!=0), excluding the diagonal. DRAM-bound.
// =====================================================================
__global__ void __launch_bounds__(256) adj_kernel(const float* __restrict__ Yr,
                                                  const float* __restrict__ Yi) {
    const int warp = (blockIdx.x * blockDim.x + threadIdx.x) >> 5; // global row
    const int lane = threadIdx.x & 31;
    if (warp >= TOTROWS) return;
    const int i = warp & (NN - 1);
    const float* yr = Yr + (size_t)warp * NN;
    const float* yi = Yi + (size_t)warp * NN;
    short* cols = g_col + (size_t)warp * MAXN;

    int count = 0;
    #pragma unroll 4
    for (int j0 = 0; j0 < NN; j0 += 32) {
        const int j = j0 + lane;
        const bool nz = (j != i) && ((yr[j] != 0.0f) || (yi[j] != 0.0f));
        const unsigned m = __ballot_sync(0xffffffffu, nz);
        if (nz) {
            const int pos = count + __popc(m & ((1u << lane) - 1u));
            if (pos < MAXN) cols[pos] = (short)j;
        }
        count += __popc(m);
    }
    if (lane == 0) {
        g_deg[warp] = count < MAXN ? count : MAXN;
        g_inv[warp] = 1.0f / (float)(count > 1 ? count : 1);
    }
}

// =====================================================================
// Kernel 2: role-selected embedding. One block per node, thread = d.
// Writes fp32 master and bf16 mirror.
// =====================================================================
__global__ void __launch_bounds__(256) emb_kernel(const int*   __restrict__ bus_type,
                                                  const float* __restrict__ features,
                                                  const float* __restrict__ W_emb,
                                                  const float* __restrict__ b_emb) {
    const int node = blockIdx.x;
    const int d = threadIdx.x;
    const int r = bus_type[node] - 1;          // 0..2
    const float f0 = features[node * 2 + 0];
    const float f1 = features[node * 2 + 1];
    const float w0 = W_emb[(r * 2 + 0) * DD + d];
    const float w1 = W_emb[(r * 2 + 1) * DD + d];
    const float h = tanhf(fmaf(f0, w0, fmaf(f1, w1, b_emb[r * DD + d])));
    g_H  [(size_t)node * DD + d] = h;
    g_Hbf[(size_t)node * DD + d] = __float2bfloat16(h);
}

// =====================================================================
// Kernel 3: SpMM  AH[row,:] = inv * sum_{j in nbrs(row)} Hbf[j,:]
// One warp per row (4 rows sequential). Lane owns d = lane*8..lane*8+7.
// bf16 gather: 512B per neighbor row (half the fp32 traffic), fp32 accum.
// =====================================================================
__device__ __forceinline__ void accum_bf16x8(float a[8], const uint4 v) {
    float2 f;
    f = __bfloat1622float2(*reinterpret_cast<const __nv_bfloat162*>(&v.x));
    a[0] += f.x; a[1] += f.y;
    f = __bfloat1622float2(*reinterpret_cast<const __nv_bfloat162*>(&v.y));
    a[2] += f.x; a[3] += f.y;
    f = __bfloat1622float2(*reinterpret_cast<const __nv_bfloat162*>(&v.z));
    a[4] += f.x; a[5] += f.y;
    f = __bfloat1622float2(*reinterpret_cast<const __nv_bfloat162*>(&v.w));
    a[6] += f.x; a[7] += f.y;
}

__global__ void __launch_bounds__(256) spmm_kernel() {
    const int lane = threadIdx.x & 31;
    const int warp = threadIdx.x >> 5;
    const int row0 = blockIdx.x * 32 + warp * 4;

    for (int rr = 0; rr < 4; ++rr) {
        const int row = row0 + rr;
        const int b = row >> 11;
        const __nv_bfloat16* __restrict__ Hb = g_Hbf + (size_t)b * NN * DD;
        const short* __restrict__ cols = g_col + (size_t)row * MAXN;
        const int deg = g_deg[row];
        const float inv = g_inv[row];

        float a[8];
        #pragma unroll
        for (int q = 0; q < 8; ++q) a[q] = 0.0f;

        int t = 0;
        for (; t + 4 <= deg; t += 4) {
            const int j0 = cols[t], j1 = cols[t + 1], j2 = cols[t + 2], j3 = cols[t + 3];
            const uint4 v0 = *((const uint4*)(Hb + (size_t)j0 * DD) + lane);
            const uint4 v1 = *((const uint4*)(Hb + (size_t)j1 * DD) + lane);
            const uint4 v2 = *((const uint4*)(Hb + (size_t)j2 * DD) + lane);
            const uint4 v3 = *((const uint4*)(Hb + (size_t)j3 * DD) + lane);
            accum_bf16x8(a, v0);
            accum_bf16x8(a, v1);
            accum_bf16x8(a, v2);
            accum_bf16x8(a, v3);
        }
        for (; t < deg; ++t) {
            const int j0 = cols[t];
            const uint4 v0 = *((const uint4*)(Hb + (size_t)j0 * DD) + lane);
            accum_bf16x8(a, v0);
        }

        float4* outp = (float4*)(g_AH + (size_t)row * DD);
        outp[lane * 2 + 0] = make_float4(a[0] * inv, a[1] * inv, a[2] * inv, a[3] * inv);
        outp[lane * 2 + 1] = make_float4(a[4] * inv, a[5] * inv, a[6] * inv, a[7] * inv);
    }
}

// =====================================================================
// Kernel 4: dense update  H += tanh(AH @ Wl + bl)  (in-place on H:
// legal because the sparse gather consumed AH into g_AH already).
// SGEMM M=16384, N=256(full), K=256. CTA tile 128x256 (grid=128, one
// wave), thread tile 8m x 16n as 4 column-quads (n0, n0+64, +128, +192)
// for conflict-minimal 16B-stride SMEM reads. Inner math uses packed
// fma.rn.f32x2 (FFMA2): 2 FMAs per issue slot -> 128 FMA/cyc/SM.
// =====================================================================
__global__ void __launch_bounds__(256, 1) update_kernel(const float* __restrict__ Wl,
                                                        const float* __restrict__ bl) {
    __shared__ float As[8][132];   // [k][m], transposed A chunk
    __shared__ float Bs[8][260];   // [k][n], full 256-wide Wl chunk

    const int tid   = threadIdx.x;
    const int mBase = blockIdx.x * 128;

    // global-load indices
    const int mA = tid >> 1;            // 0..127
    const int hA = (tid & 1) * 4;       // 0 or 4 (k offset within chunk)
    const int kB = tid >> 5;            // 0..7
    const int nB = (tid & 31) * 8;      // 0..248

    // compute indices
    const int m0 = (tid >> 4) * 8;      // 0..120
    const int n0 = (tid & 15) * 4;      // 0..60; quads at n0 + 64*q

    unsigned long long acc2[8][8];
    #pragma unroll
    for (int i = 0; i < 8; ++i)
        #pragma unroll
        for (int j = 0; j < 8; ++j) acc2[i][j] = 0ULL;

    const float* aPtr = g_AH + (size_t)(mBase + mA) * DD + hA;
    const float* bPtr = Wl + (size_t)kB * DD + nB;

    // prefetch chunk 0
    float4 av  = *(const float4*)(aPtr);
    float4 bv0 = *(const float4*)(bPtr);
    float4 bv1 = *(const float4*)(bPtr + 4);

    for (int kk = 0; kk < DD; kk += 8) {
        As[hA + 0][mA] = av.x; As[hA + 1][mA] = av.y;
        As[hA + 2][mA] = av.z; As[hA + 3][mA] = av.w;
        *(float4*)&Bs[kB][nB]     = bv0;
        *(float4*)&Bs[kB][nB + 4] = bv1;
        __syncthreads();

        if (kk + 8 < DD) {
            av  = *(const float4*)(aPtr + kk + 8);
            bv0 = *(const float4*)(bPtr + (size_t)(kk + 8) * DD);
            bv1 = *(const float4*)(bPtr + (size_t)(kk + 8) * DD + 4);
        }

        #pragma unroll
        for (int k = 0; k < 8; ++k) {
            const float4 a0 = *(const float4*)&As[k][m0];
            const float4 a1 = *(const float4*)&As[k][m0 + 4];
            unsigned long long am2[8];
            am2[0] = pack2(a0.x); am2[1] = pack2(a0.y);
            am2[2] = pack2(a0.z); am2[3] = pack2(a0.w);
            am2[4] = pack2(a1.x); am2[5] = pack2(a1.y);
            am2[6] = pack2(a1.z); am2[7] = pack2(a1.w);

            unsigned long long bn2[8];
            #pragma unroll
            for (int q = 0; q < 4; ++q) {
                const ulonglong2 bq = *(const ulonglong2*)&Bs[k][n0 + 64 * q];
                bn2[2 * q + 0] = bq.x;
                bn2[2 * q + 1] = bq.y;
            }

            #pragma unroll
            for (int i = 0; i < 8; ++i)
                #pragma unroll
                for (int j = 0; j < 8; ++j)
                    FMA2(acc2[i][j], am2[i], bn2[j]);
        }
        __syncthreads();
    }

    // fused epilogue: H[row, col] += tanh(acc + bl[col]); refresh bf16 mirror
    float4 blq[4];
    #pragma unroll
    for (int q = 0; q < 4; ++q) blq[q] = *(const float4*)(bl + n0 + 64 * q);

    #pragma unroll
    for (int i = 0; i < 8; ++i) {
        const int m = mBase + m0 + i;
        float*         Hrow  = g_H   + (size_t)m * DD;
        __nv_bfloat16* Hbrow = g_Hbf + (size_t)m * DD;
        #pragma unroll
        for (int q = 0; q < 4; ++q) {
            const int c = n0 + 64 * q;
            float lo0, hi0, lo1, hi1;
            unpack2(acc2[i][2 * q + 0], lo0, hi0);
            unpack2(acc2[i][2 * q + 1], lo1, hi1);
            float4 h = *(float4*)(Hrow + c);
            h.x += tanhf(lo0 + blq[q].x);
            h.y += tanhf(hi0 + blq[q].y);
            h.z += tanhf(lo1 + blq[q].z);
            h.w += tanhf(hi1 + blq[q].w);
            *(float4*)(Hrow + c) = h;
            const __nv_bfloat162 p0 = __floats2bfloat162_rn(h.x, h.y);
            const __nv_bfloat162 p1 = __floats2bfloat162_rn(h.z, h.w);
            uint2 st;
            st.x = *reinterpret_cast<const unsigned*>(&p0);
            st.y = *reinterpret_cast<const unsigned*>(&p1);
            *(uint2*)(Hbrow + c) = st;
        }
    }
}

// =====================================================================
// Kernel 5: decoder. Block = batch. Column sums over nodes (coalesced),
// then tiny GEMV. Reads the fp32 master H.
// =====================================================================
__global__ void __launch_bounds__(256) decoder_kernel(const float* __restrict__ Wd,
                                                      const float* __restrict__ bd,
                                                      float* __restrict__ out) {
    const int b = blockIdx.x;
    const int d = threadIdx.x;
    const float* Hb = g_H + (size_t)b * NN * DD;

    float s0 = 0.f, s1 = 0.f, s2 = 0.f, s3 = 0.f;
    #pragma unroll 1
    for (int n = 0; n < NN; n += 4) {
        s0 += Hb[(size_t)(n + 0) * DD + d];
        s1 += Hb[(size_t)(n + 1) * DD + d];
        s2 += Hb[(size_t)(n + 2) * DD + d];
        s3 += Hb[(size_t)(n + 3) * DD + d];
    }
    __shared__ float mean[DD];
    mean[d] = (s0 + s1 + s2 + s3) * (1.0f / (float)NN);
    __syncthreads();

    if (d < OUTD) {
        float o = bd[d];
        #pragma unroll 8
        for (int k = 0; k < DD; ++k)
            o = fmaf(mean[k], Wd[k * OUTD + d], o);
        out[b * OUTD + d] = o;
    }
}

// =====================================================================
// Launch. Inputs (metadata order): 0 bus_type(i32), 1 Yr, 2 Yi,
// 3 features, 4 W_emb, 5 b_emb, 6 Wl, 7 bl, 8 Wd, 9 bd.
// Output: float[8*15].
// =====================================================================
extern "C" void kernel_launch(void* const* d_in, const int* in_sizes, int n_in,
                              void* d_out, int out_size) {
    const int*   bus_type = (const int*)  d_in[0];
    const float* Yr       = (const float*)d_in[1];
    const float* Yi       = (const float*)d_in[2];
    const float* features = (const float*)d_in[3];
    const float* W_emb    = (const float*)d_in[4];
    const float* b_emb    = (const float*)d_in[5];
    const float* Wl       = (const float*)d_in[6];
    const float* bl       = (const float*)d_in[7];
    const float* Wd       = (const float*)d_in[8];
    const float* bd       = (const float*)d_in[9];
    float* out = (float*)d_out;

    adj_kernel<<<TOTROWS / 8, 256>>>(Yr, Yi);
    emb_kernel<<<TOTROWS, 256>>>(bus_type, features, W_emb, b_emb);

    for (int k = 0; k < KSTEPS; ++k) {
        spmm_kernel<<<TOTROWS / 32, 256>>>();
        update_kernel<<<TOTROWS / 128, 256>>>(Wl, bl);
    }

    decoder_kernel<<<BB, 256>>>(Wd, bd, out);
}